// round 6
// baseline (speedup 1.0000x reference)
#include <cuda_runtime.h>
#include <cuda_bf16.h>
#include <math.h>
#include <stdint.h>

#define BB 2
#define CC 512
#define SS 8192
#define NHW 1024
#define SQRT_C     22.627416997969522f
#define INV_SQRT_C 0.04419417382415922f

#define KSLAB  32
#define KMP 136            // KM tile row stride (bf16)
#define MKP 40             // MK tile row stride (bf16)
#define SZ_KM (32 * KMP * 2)    // 8704 B
#define SZ_MK (128 * MKP * 2)   // 10240 B

#define SMEM_QK   (4 * 2 * SZ_KM)            // 69632
#define SMEM_QKV  (4 * (SZ_MK + SZ_KM))      // 75776
#define SMEM_PV   (3 * 2 * SZ_MK)            // 61440
#define SMEM_OP   (3 * 2 * SZ_MK)            // 61440

// Scratch (bf16 intermediates)
__device__ __nv_bfloat16 g_hn[(size_t)BB * CC * SS];   // [b][c][s]
__device__ __nv_bfloat16 g_q [(size_t)BB * CC * SS];   // [b][c][s]
__device__ __nv_bfloat16 g_k [(size_t)BB * CC * SS];   // [b][c][s]
__device__ __nv_bfloat16 g_v [(size_t)BB * CC * SS];   // [b][c][s]
__device__ __nv_bfloat16 g_p [(size_t)BB * SS * SS];   // [b][sq][sk]  (exp, unnormalized)
__device__ __nv_bfloat16 g_o [(size_t)BB * SS * CC];   // [b][s][c]
__device__ __nv_bfloat16 g_w [4][(size_t)CC * CC];     // bf16 weights [co][ci]
__device__ float g_rsum[(size_t)BB * SS];              // row sums of exp

// ---------------------------------------------------------------------------
// PTX helpers
// ---------------------------------------------------------------------------
__device__ __forceinline__ uint32_t smaddr(const void* p) {
    return (uint32_t)__cvta_generic_to_shared(p);
}
__device__ __forceinline__ void cp16(uint32_t d, const void* s) {
    asm volatile("cp.async.cg.shared.global [%0], [%1], 16;\n" :: "r"(d), "l"(s));
}
__device__ __forceinline__ void cp_commit() { asm volatile("cp.async.commit_group;\n"); }
template<int N> __device__ __forceinline__ void cp_wait() {
    asm volatile("cp.async.wait_group %0;\n" :: "n"(N));
}
__device__ __forceinline__ void ldsm4(uint32_t* r, uint32_t a) {
    asm volatile("ldmatrix.sync.aligned.m8n8.x4.shared.b16 {%0,%1,%2,%3}, [%4];"
                 : "=r"(r[0]), "=r"(r[1]), "=r"(r[2]), "=r"(r[3]) : "r"(a));
}
__device__ __forceinline__ void ldsm4t(uint32_t* r, uint32_t a) {
    asm volatile("ldmatrix.sync.aligned.m8n8.x4.trans.shared.b16 {%0,%1,%2,%3}, [%4];"
                 : "=r"(r[0]), "=r"(r[1]), "=r"(r[2]), "=r"(r[3]) : "r"(a));
}
__device__ __forceinline__ void mma16816(float* c, const uint32_t* a, const uint32_t* b) {
    asm volatile("mma.sync.aligned.m16n8k16.row.col.f32.bf16.bf16.f32 "
                 "{%0,%1,%2,%3},{%4,%5,%6,%7},{%8,%9},{%0,%1,%2,%3};"
                 : "+f"(c[0]), "+f"(c[1]), "+f"(c[2]), "+f"(c[3])
                 : "r"(a[0]), "r"(a[1]), "r"(a[2]), "r"(a[3]), "r"(b[0]), "r"(b[1]));
}

// ---------------------------------------------------------------------------
// stagers: 128 threads, 4 x 16B chunks each
// ---------------------------------------------------------------------------
__device__ __forceinline__ void stageKM(uint32_t dst, const __nv_bfloat16* g,
                                        int ld, int k0, int n0, int tid) {
#pragma unroll
    for (int j = 0; j < 4; j++) {
        int c = j * 128 + tid;
        int kr = c >> 4, off = (c & 15) << 3;
        cp16(dst + (uint32_t)(kr * KMP + off) * 2, g + (size_t)(k0 + kr) * ld + n0 + off);
    }
}
__device__ __forceinline__ void stageMK(uint32_t dst, const __nv_bfloat16* g,
                                        int ld, int r0, int k0, int tid) {
#pragma unroll
    for (int j = 0; j < 4; j++) {
        int c = j * 128 + tid;
        int row = c >> 2, off = (c & 3) << 3;
        cp16(dst + (uint32_t)(row * MKP + off) * 2, g + (size_t)(r0 + row) * ld + k0 + off);
    }
}

// ---------------------------------------------------------------------------
// fragment loaders (warp tile 64x64, K-slab 32)
// ---------------------------------------------------------------------------
__device__ __forceinline__ void fragA_KM(uint32_t a[4][4], uint32_t base,
                                         int wm, int lane, int ks) {
    int g = lane >> 3;
#pragma unroll
    for (int mt = 0; mt < 4; mt++) {
        int row = ks * 16 + ((g >> 1) << 3) + (lane & 7);
        int col = wm + mt * 16 + ((g & 1) << 3);
        ldsm4t(a[mt], base + (uint32_t)(row * KMP + col) * 2);
    }
}
__device__ __forceinline__ void fragA_MK(uint32_t a[4][4], uint32_t base,
                                         int wm, int lane, int ks) {
    int g = lane >> 3;
#pragma unroll
    for (int mt = 0; mt < 4; mt++) {
        int row = wm + mt * 16 + ((g & 1) << 3) + (lane & 7);
        int col = ks * 16 + ((g >> 1) << 3);
        ldsm4(a[mt], base + (uint32_t)(row * MKP + col) * 2);
    }
}
__device__ __forceinline__ void fragB_KM(uint32_t b[8][4], uint32_t base, int wn, int lane) {
    int g = lane >> 3;
#pragma unroll
    for (int nt = 0; nt < 8; nt++) {
        int row = (g << 3) + (lane & 7);
        int col = wn + nt * 8;
        ldsm4t(b[nt], base + (uint32_t)(row * KMP + col) * 2);
    }
}
__device__ __forceinline__ void fragB_MK(uint32_t b[8][4], uint32_t base, int wn, int lane) {
    int g = lane >> 3;
#pragma unroll
    for (int nt = 0; nt < 8; nt++) {
        int row = wn + nt * 8 + (lane & 7);
        int col = g << 3;
        ldsm4(b[nt], base + (uint32_t)(row * MKP + col) * 2);
    }
}

#define GEMM_VARS                                                     \
    extern __shared__ __align__(16) char dynsm[];                     \
    uint32_t sbase = smaddr(dynsm);                                   \
    int tid = threadIdx.x, lane = tid & 31, wid = tid >> 5;           \
    int wm = (wid >> 1) * 64, wn = (wid & 1) * 64;                    \
    int qr = lane >> 2, qc = lane & 3;                                \
    float acc[4][8][4];                                               \
    _Pragma("unroll") for (int mt = 0; mt < 4; mt++)                  \
    _Pragma("unroll") for (int nt = 0; nt < 8; nt++)                  \
    _Pragma("unroll") for (int i = 0; i < 4; i++) acc[mt][nt][i] = 0.f;

#define SLAB_COMPUTE(FA, FB, baseA, baseB)                            \
    {                                                                 \
        uint32_t bfr[8][4];                                           \
        FB(bfr, (baseB), wn, lane);                                   \
        _Pragma("unroll")                                             \
        for (int ks = 0; ks < 2; ks++) {                              \
            uint32_t afr[4][4];                                       \
            FA(afr, (baseA), wm, lane, ks);                           \
            _Pragma("unroll") for (int mt = 0; mt < 4; mt++)          \
            _Pragma("unroll") for (int nt = 0; nt < 8; nt++)          \
                mma16816(acc[mt][nt], afr[mt], &bfr[nt][ks * 2]);     \
        }                                                             \
    }

// ---------------------------------------------------------------------------
// prep: fp32 weights -> bf16
// ---------------------------------------------------------------------------
__global__ void prep_w_kernel(const float* __restrict__ wq, const float* __restrict__ wk,
                              const float* __restrict__ wv, const float* __restrict__ wo) {
    int which = blockIdx.y;
    const float* w = which == 0 ? wq : which == 1 ? wk : which == 2 ? wv : wo;
    int i = blockIdx.x * 256 + threadIdx.x;
    g_w[which][i] = __float2bfloat16_rn(w[i]);
}

// ---------------------------------------------------------------------------
// RMS norm (bf16 out, [c][s])
// ---------------------------------------------------------------------------
__global__ void rms_kernel(const float* __restrict__ x,
                           const float* __restrict__ gamma) {
    int s = blockIdx.x * blockDim.x + threadIdx.x;
    int b = blockIdx.y;
    const float* xb = x + (size_t)b * CC * SS + s;
    float ss = 0.f;
#pragma unroll 8
    for (int c = 0; c < CC; c++) {
        float v = xb[(size_t)c * SS];
        ss += v * v;
    }
    float scale = SQRT_C / fmaxf(sqrtf(ss), 1e-12f);
    __nv_bfloat16* hb = g_hn + (size_t)b * CC * SS + s;
#pragma unroll 8
    for (int c = 0; c < CC; c++)
        hb[(size_t)c * SS] = __float2bfloat16_rn(xb[(size_t)c * SS] * scale * gamma[c]);
}

// ---------------------------------------------------------------------------
// QKV projection: D[co][s] = W[co][:] . hn[:][s]   A = W (MK), B = hn (KM)
// ---------------------------------------------------------------------------
__global__ void __launch_bounds__(128, 3) qkv_kernel(
    const float* __restrict__ bq, const float* __restrict__ bk,
    const float* __restrict__ bv) {

    int which = blockIdx.z % 3;
    int b     = blockIdx.z / 3;
    const __nv_bfloat16* W = g_w[which];
    const float* bias = which == 0 ? bq : (which == 1 ? bk : bv);
    __nv_bfloat16* Cout = (which == 0 ? g_q : (which == 1 ? g_k : g_v)) + (size_t)b * CC * SS;
    const __nv_bfloat16* HN = g_hn + (size_t)b * CC * SS;

    int m0 = blockIdx.y * 128, n0 = blockIdx.x * 128;
    GEMM_VARS
    uint32_t tbA = sbase, tbB = sbase + 4 * SZ_MK;

    for (int s = 0; s < 3; s++) {
        stageMK(tbA + s * SZ_MK, W, CC, m0, s * KSLAB, tid);
        stageKM(tbB + s * SZ_KM, HN, SS, s * KSLAB, n0, tid);
        cp_commit();
    }
    const int nIt = CC / KSLAB;   // 16
    for (int i = 0; i < nIt; i++) {
        cp_wait<2>();
        __syncthreads();
        int sl = i & 3;
        SLAB_COMPUTE(fragA_MK, fragB_KM, tbA + sl * SZ_MK, tbB + sl * SZ_KM);
        int pf = i + 3;
        if (pf < nIt) {
            int ps = pf & 3;
            stageMK(tbA + ps * SZ_MK, W, CC, m0, pf * KSLAB, tid);
            stageKM(tbB + ps * SZ_KM, HN, SS, pf * KSLAB, n0, tid);
            cp_commit();
        }
    }

#pragma unroll
    for (int mt = 0; mt < 4; mt++) {
        int m = m0 + wm + mt * 16 + qr;
        float bi0 = bias[m], bi1 = bias[m + 8];
#pragma unroll
        for (int nt = 0; nt < 8; nt++) {
            int n = n0 + wn + nt * 8 + qc * 2;
            *(__nv_bfloat162*)&Cout[(size_t)m * SS + n] =
                __floats2bfloat162_rn(acc[mt][nt][0] + bi0, acc[mt][nt][1] + bi0);
            *(__nv_bfloat162*)&Cout[(size_t)(m + 8) * SS + n] =
                __floats2bfloat162_rn(acc[mt][nt][2] + bi1, acc[mt][nt][3] + bi1);
        }
    }
}

// ---------------------------------------------------------------------------
// QK^T (allowed tiles only): A = Q (KM), B = K (KM); write exp(scores) bf16
// ---------------------------------------------------------------------------
__global__ void __launch_bounds__(128, 3) qk_kernel() {
    int b  = blockIdx.z;
    int m0 = blockIdx.y * 128;   // sq
    int n0 = blockIdx.x * 128;   // sk
    if (n0 / NHW > m0 / NHW) return;

    const __nv_bfloat16* Q = g_q + (size_t)b * CC * SS;
    const __nv_bfloat16* K = g_k + (size_t)b * CC * SS;
    GEMM_VARS
    uint32_t tbA = sbase, tbB = sbase + 4 * SZ_KM;

    for (int s = 0; s < 3; s++) {
        stageKM(tbA + s * SZ_KM, Q, SS, s * KSLAB, m0, tid);
        stageKM(tbB + s * SZ_KM, K, SS, s * KSLAB, n0, tid);
        cp_commit();
    }
    const int nIt = CC / KSLAB;
    for (int i = 0; i < nIt; i++) {
        cp_wait<2>();
        __syncthreads();
        int sl = i & 3;
        SLAB_COMPUTE(fragA_KM, fragB_KM, tbA + sl * SZ_KM, tbB + sl * SZ_KM);
        int pf = i + 3;
        if (pf < nIt) {
            int ps = pf & 3;
            stageKM(tbA + ps * SZ_KM, Q, SS, pf * KSLAB, m0, tid);
            stageKM(tbB + ps * SZ_KM, K, SS, pf * KSLAB, n0, tid);
            cp_commit();
        }
    }

    __nv_bfloat16* P = g_p + (size_t)b * SS * SS;
#pragma unroll
    for (int mt = 0; mt < 4; mt++) {
        int m = m0 + wm + mt * 16 + qr;
#pragma unroll
        for (int nt = 0; nt < 8; nt++) {
            int n = n0 + wn + nt * 8 + qc * 2;
            *(__nv_bfloat162*)&P[(size_t)m * SS + n] =
                __floats2bfloat162_rn(__expf(acc[mt][nt][0] * INV_SQRT_C),
                                      __expf(acc[mt][nt][1] * INV_SQRT_C));
            *(__nv_bfloat162*)&P[(size_t)(m + 8) * SS + n] =
                __floats2bfloat162_rn(__expf(acc[mt][nt][2] * INV_SQRT_C),
                                      __expf(acc[mt][nt][3] * INV_SQRT_C));
        }
    }
}

// ---------------------------------------------------------------------------
// row sums of exp(scores): g_rsum[b][sq] = sum_k P[sq][k]
// ---------------------------------------------------------------------------
__global__ void __launch_bounds__(256) rsum_kernel() {
    int sq = blockIdx.x;
    int b  = blockIdx.y;
    const __nv_bfloat162* row2 = (const __nv_bfloat162*)(g_p + ((size_t)b * SS + sq) * SS);
    int L = (sq / NHW + 1) * NHW;
    int n2 = L >> 9;
    int tid = threadIdx.x, lane = tid & 31, wid = tid >> 5;

    __shared__ float red[8];
    float s = 0.f;
#pragma unroll
    for (int i = 0; i < 16; i++)
        if (i < n2) {
            float2 v = __bfloat1622float2(row2[i * 256 + tid]);
            s += v.x + v.y;
        }
#pragma unroll
    for (int o = 16; o > 0; o >>= 1) s += __shfl_xor_sync(0xffffffffu, s, o);
    if (lane == 0) red[wid] = s;
    __syncthreads();
    if (tid == 0) {
        float S = 0.f;
#pragma unroll
        for (int i = 0; i < 8; i++) S += red[i];
        g_rsum[b * SS + sq] = S;
    }
}

// ---------------------------------------------------------------------------
// PV: D[sq][c] = (P[sq][:L] . v[c][:L]) / rsum[sq]   (3-stage)
// ---------------------------------------------------------------------------
__global__ void __launch_bounds__(128, 3) pv_kernel() {
    int b  = blockIdx.z;
    int m0 = blockIdx.y * 128;   // sq
    int n0 = blockIdx.x * 128;   // c
    int L  = (m0 / NHW + 1) * NHW;
    const int nIt = L / KSLAB;

    const __nv_bfloat16* P = g_p + (size_t)b * SS * SS;
    const __nv_bfloat16* V = g_v + (size_t)b * CC * SS;
    GEMM_VARS
    uint32_t tbA = sbase, tbB = sbase + 3 * SZ_MK;

    for (int s = 0; s < 2; s++) {
        stageMK(tbA + s * SZ_MK, P, SS, m0, s * KSLAB, tid);
        stageMK(tbB + s * SZ_MK, V, SS, n0, s * KSLAB, tid);
        cp_commit();
    }
    for (int i = 0; i < nIt; i++) {
        cp_wait<1>();
        __syncthreads();
        int sl = i % 3;
        SLAB_COMPUTE(fragA_MK, fragB_MK, tbA + sl * SZ_MK, tbB + sl * SZ_MK);
        int pf = i + 2;
        if (pf < nIt) {
            int ps = pf % 3;
            stageMK(tbA + ps * SZ_MK, P, SS, m0, pf * KSLAB, tid);
            stageMK(tbB + ps * SZ_MK, V, SS, n0, pf * KSLAB, tid);
            cp_commit();
        }
    }

    __nv_bfloat16* O = g_o + (size_t)b * SS * CC;
#pragma unroll
    for (int mt = 0; mt < 4; mt++) {
        int m = m0 + wm + mt * 16 + qr;
        float inv0 = 1.f / g_rsum[b * SS + m];
        float inv1 = 1.f / g_rsum[b * SS + m + 8];
#pragma unroll
        for (int nt = 0; nt < 8; nt++) {
            int n = n0 + wn + nt * 8 + qc * 2;
            *(__nv_bfloat162*)&O[(size_t)m * CC + n] =
                __floats2bfloat162_rn(acc[mt][nt][0] * inv0, acc[mt][nt][1] * inv0);
            *(__nv_bfloat162*)&O[(size_t)(m + 8) * CC + n] =
                __floats2bfloat162_rn(acc[mt][nt][2] * inv1, acc[mt][nt][3] * inv1);
        }
    }
}

// ---------------------------------------------------------------------------
// O-proj + residual (fp32 out): A = wo (MK), B = g_o (MK rows s)  (3-stage)
// ---------------------------------------------------------------------------
__global__ void __launch_bounds__(128, 3) oproj_kernel(
    const float* __restrict__ bo, const float* __restrict__ x,
    float* __restrict__ out) {

    int b  = blockIdx.z;
    int m0 = blockIdx.y * 128;   // c_out
    int n0 = blockIdx.x * 128;   // s

    const __nv_bfloat16* W = g_w[3];
    const __nv_bfloat16* O = g_o + (size_t)b * SS * CC;
    GEMM_VARS
    uint32_t tbA = sbase, tbB = sbase + 3 * SZ_MK;

    for (int s = 0; s < 2; s++) {
        stageMK(tbA + s * SZ_MK, W, CC, m0, s * KSLAB, tid);
        stageMK(tbB + s * SZ_MK, O, CC, n0, s * KSLAB, tid);
        cp_commit();
    }
    const int nIt = CC / KSLAB;
    for (int i = 0; i < nIt; i++) {
        cp_wait<1>();
        __syncthreads();
        int sl = i % 3;
        SLAB_COMPUTE(fragA_MK, fragB_MK, tbA + sl * SZ_MK, tbB + sl * SZ_MK);
        int pf = i + 2;
        if (pf < nIt) {
            int ps = pf % 3;
            stageMK(tbA + ps * SZ_MK, W, CC, m0, pf * KSLAB, tid);
            stageMK(tbB + ps * SZ_MK, O, CC, n0, pf * KSLAB, tid);
            cp_commit();
        }
    }

#pragma unroll
    for (int mt = 0; mt < 4; mt++) {
        int m = m0 + wm + mt * 16 + qr;
        float bi0 = bo[m], bi1 = bo[m + 8];
#pragma unroll
        for (int nt = 0; nt < 8; nt++) {
            int n = n0 + wn + nt * 8 + qc * 2;
            const float2 x0 = *(const float2*)&x[((size_t)b * CC + m) * SS + n];
            const float2 x1 = *(const float2*)&x[((size_t)b * CC + m + 8) * SS + n];
            float2 v0 = make_float2(acc[mt][nt][0] + bi0 + x0.x, acc[mt][nt][1] + bi0 + x0.y);
            float2 v1 = make_float2(acc[mt][nt][2] + bi1 + x1.x, acc[mt][nt][3] + bi1 + x1.y);
            *(float2*)&out[((size_t)b * CC + m) * SS + n]     = v0;
            *(float2*)&out[((size_t)b * CC + m + 8) * SS + n] = v1;
        }
    }
}

// ---------------------------------------------------------------------------
extern "C" void kernel_launch(void* const* d_in, const int* in_sizes, int n_in,
                              void* d_out, int out_size) {
    const float* x     = (const float*)d_in[0];
    const float* gamma = (const float*)d_in[1];
    const float* wq    = (const float*)d_in[2];
    const float* bq    = (const float*)d_in[3];
    const float* wk    = (const float*)d_in[4];
    const float* bk    = (const float*)d_in[5];
    const float* wv    = (const float*)d_in[6];
    const float* bv    = (const float*)d_in[7];
    const float* wo    = (const float*)d_in[8];
    const float* bo    = (const float*)d_in[9];
    float* out = (float*)d_out;

    static int attr_done = 0;
    if (!attr_done) {
        cudaFuncSetAttribute(qkv_kernel,   cudaFuncAttributeMaxDynamicSharedMemorySize, SMEM_QKV);
        cudaFuncSetAttribute(qk_kernel,    cudaFuncAttributeMaxDynamicSharedMemorySize, SMEM_QK);
        cudaFuncSetAttribute(pv_kernel,    cudaFuncAttributeMaxDynamicSharedMemorySize, SMEM_PV);
        cudaFuncSetAttribute(oproj_kernel, cudaFuncAttributeMaxDynamicSharedMemorySize, SMEM_OP);
        attr_done = 1;
    }

    prep_w_kernel<<<dim3(CC * CC / 256, 4), 256>>>(wq, wk, wv, wo);
    rms_kernel<<<dim3(SS / 256, BB), 256>>>(x, gamma);
    qkv_kernel<<<dim3(SS / 128, CC / 128, BB * 3), 128, SMEM_QKV>>>(bq, bk, bv);
    qk_kernel<<<dim3(SS / 128, SS / 128, BB), 128, SMEM_QK>>>();
    rsum_kernel<<<dim3(SS, BB), 256>>>();
    pv_kernel<<<dim3(CC / 128, SS / 128, BB), 128, SMEM_PV>>>();
    oproj_kernel<<<dim3(SS / 128, CC / 128, BB), 128, SMEM_OP>>>(bo, x, out);
}

// round 7
// speedup vs baseline: 1.3192x; 1.3192x over previous
#include <cuda_runtime.h>
#include <cuda_bf16.h>
#include <math.h>
#include <stdint.h>

#define BB 2
#define CC 512
#define SS 8192
#define NHW 1024
#define SQRT_C     22.627416997969522f
#define INV_SQRT_C 0.04419417382415922f

#define STAGES 4
#define KSLAB  32
#define KMP 136            // KM tile row stride (bf16)
#define MKP 40             // MK tile row stride (bf16)
#define SZ_KM (32 * KMP * 2)    // 8704 B
#define SZ_MK (128 * MKP * 2)   // 10240 B
#define DYN_SMEM (2 * STAGES * SZ_MK)   // 81920 B

// Scratch (bf16 intermediates)
__device__ __nv_bfloat16 g_hn[(size_t)BB * CC * SS];   // [b][c][s]
__device__ __nv_bfloat16 g_q [(size_t)BB * CC * SS];   // [b][c][s]
__device__ __nv_bfloat16 g_k [(size_t)BB * CC * SS];   // [b][c][s]
__device__ __nv_bfloat16 g_v [(size_t)BB * CC * SS];   // [b][c][s]
__device__ __nv_bfloat16 g_p [(size_t)BB * SS * SS];   // [b][sq][sk] (exp, unnormalized)
__device__ __nv_bfloat16 g_o [(size_t)BB * SS * CC];   // [b][s][c]
__device__ __nv_bfloat16 g_w [4][(size_t)CC * CC];     // bf16 weights [co][ci]
__device__ float g_rsum[(size_t)BB * SS];              // row sums of exp

// ---------------------------------------------------------------------------
// PTX helpers
// ---------------------------------------------------------------------------
__device__ __forceinline__ uint32_t smaddr(const void* p) {
    return (uint32_t)__cvta_generic_to_shared(p);
}
__device__ __forceinline__ void cp16(uint32_t d, const void* s) {
    asm volatile("cp.async.cg.shared.global [%0], [%1], 16;\n" :: "r"(d), "l"(s));
}
__device__ __forceinline__ void cp_commit() { asm volatile("cp.async.commit_group;\n"); }
template<int N> __device__ __forceinline__ void cp_wait() {
    asm volatile("cp.async.wait_group %0;\n" :: "n"(N));
}
__device__ __forceinline__ void ldsm4(uint32_t* r, uint32_t a) {
    asm volatile("ldmatrix.sync.aligned.m8n8.x4.shared.b16 {%0,%1,%2,%3}, [%4];"
                 : "=r"(r[0]), "=r"(r[1]), "=r"(r[2]), "=r"(r[3]) : "r"(a));
}
__device__ __forceinline__ void ldsm4t(uint32_t* r, uint32_t a) {
    asm volatile("ldmatrix.sync.aligned.m8n8.x4.trans.shared.b16 {%0,%1,%2,%3}, [%4];"
                 : "=r"(r[0]), "=r"(r[1]), "=r"(r[2]), "=r"(r[3]) : "r"(a));
}
__device__ __forceinline__ void mma16816(float* c, const uint32_t* a, const uint32_t* b) {
    asm volatile("mma.sync.aligned.m16n8k16.row.col.f32.bf16.bf16.f32 "
                 "{%0,%1,%2,%3},{%4,%5,%6,%7},{%8,%9},{%0,%1,%2,%3};"
                 : "+f"(c[0]), "+f"(c[1]), "+f"(c[2]), "+f"(c[3])
                 : "r"(a[0]), "r"(a[1]), "r"(a[2]), "r"(a[3]), "r"(b[0]), "r"(b[1]));
}

// ---------------------------------------------------------------------------
// stagers: 128 threads, 4 x 16B chunks each
// ---------------------------------------------------------------------------
__device__ __forceinline__ void stageKM(uint32_t dst, const __nv_bfloat16* g,
                                        int ld, int k0, int n0, int tid) {
#pragma unroll
    for (int j = 0; j < 4; j++) {
        int c = j * 128 + tid;
        int kr = c >> 4, off = (c & 15) << 3;
        cp16(dst + (uint32_t)(kr * KMP + off) * 2, g + (size_t)(k0 + kr) * ld + n0 + off);
    }
}
__device__ __forceinline__ void stageMK(uint32_t dst, const __nv_bfloat16* g,
                                        int ld, int r0, int k0, int tid) {
#pragma unroll
    for (int j = 0; j < 4; j++) {
        int c = j * 128 + tid;
        int row = c >> 2, off = (c & 3) << 3;
        cp16(dst + (uint32_t)(row * MKP + off) * 2, g + (size_t)(r0 + row) * ld + k0 + off);
    }
}

// ---------------------------------------------------------------------------
// fragment loaders (warp tile 64x64, K-slab 32)
// ---------------------------------------------------------------------------
__device__ __forceinline__ void fragA_KM(uint32_t a[4][4], uint32_t base,
                                         int wm, int lane, int ks) {
    int g = lane >> 3;
#pragma unroll
    for (int mt = 0; mt < 4; mt++) {
        int row = ks * 16 + ((g >> 1) << 3) + (lane & 7);
        int col = wm + mt * 16 + ((g & 1) << 3);
        ldsm4t(a[mt], base + (uint32_t)(row * KMP + col) * 2);
    }
}
__device__ __forceinline__ void fragA_MK(uint32_t a[4][4], uint32_t base,
                                         int wm, int lane, int ks) {
    int g = lane >> 3;
#pragma unroll
    for (int mt = 0; mt < 4; mt++) {
        int row = wm + mt * 16 + ((g & 1) << 3) + (lane & 7);
        int col = ks * 16 + ((g >> 1) << 3);
        ldsm4(a[mt], base + (uint32_t)(row * MKP + col) * 2);
    }
}
__device__ __forceinline__ void fragB_KM(uint32_t b[8][4], uint32_t base, int wn, int lane) {
    int g = lane >> 3;
#pragma unroll
    for (int nt = 0; nt < 8; nt++) {
        int row = (g << 3) + (lane & 7);
        int col = wn + nt * 8;
        ldsm4t(b[nt], base + (uint32_t)(row * KMP + col) * 2);
    }
}
__device__ __forceinline__ void fragB_MK(uint32_t b[8][4], uint32_t base, int wn, int lane) {
    int g = lane >> 3;
#pragma unroll
    for (int nt = 0; nt < 8; nt++) {
        int row = wn + nt * 8 + (lane & 7);
        int col = g << 3;
        ldsm4(b[nt], base + (uint32_t)(row * MKP + col) * 2);
    }
}

#define GEMM_VARS                                                     \
    extern __shared__ __align__(16) char dynsm[];                     \
    uint32_t sbase = smaddr(dynsm);                                   \
    int tid = threadIdx.x, lane = tid & 31, wid = tid >> 5;           \
    int wm = (wid >> 1) * 64, wn = (wid & 1) * 64;                    \
    int qr = lane >> 2, qc = lane & 3;                                \
    float acc[4][8][4];                                               \
    _Pragma("unroll") for (int mt = 0; mt < 4; mt++)                  \
    _Pragma("unroll") for (int nt = 0; nt < 8; nt++)                  \
    _Pragma("unroll") for (int i = 0; i < 4; i++) acc[mt][nt][i] = 0.f;

#define SLAB_COMPUTE(FA, FB, baseA, baseB)                            \
    {                                                                 \
        uint32_t bfr[8][4];                                           \
        FB(bfr, (baseB), wn, lane);                                   \
        _Pragma("unroll")                                             \
        for (int ks = 0; ks < 2; ks++) {                              \
            uint32_t afr[4][4];                                       \
            FA(afr, (baseA), wm, lane, ks);                           \
            _Pragma("unroll") for (int mt = 0; mt < 4; mt++)          \
            _Pragma("unroll") for (int nt = 0; nt < 8; nt++)          \
                mma16816(acc[mt][nt], afr[mt], &bfr[nt][ks * 2]);     \
        }                                                             \
    }

// ---------------------------------------------------------------------------
// prep: fp32 weights -> bf16
// ---------------------------------------------------------------------------
__global__ void prep_w_kernel(const float* __restrict__ wq, const float* __restrict__ wk,
                              const float* __restrict__ wv, const float* __restrict__ wo) {
    int which = blockIdx.y;
    const float* w = which == 0 ? wq : which == 1 ? wk : which == 2 ? wv : wo;
    int i = blockIdx.x * 256 + threadIdx.x;
    g_w[which][i] = __float2bfloat16_rn(w[i]);
}

// ---------------------------------------------------------------------------
// RMS norm (bf16 out, [c][s])
// ---------------------------------------------------------------------------
__global__ void rms_kernel(const float* __restrict__ x,
                           const float* __restrict__ gamma) {
    int s = blockIdx.x * blockDim.x + threadIdx.x;
    int b = blockIdx.y;
    const float* xb = x + (size_t)b * CC * SS + s;
    float ss = 0.f;
#pragma unroll 8
    for (int c = 0; c < CC; c++) {
        float v = xb[(size_t)c * SS];
        ss += v * v;
    }
    float scale = SQRT_C / fmaxf(sqrtf(ss), 1e-12f);
    __nv_bfloat16* hb = g_hn + (size_t)b * CC * SS + s;
#pragma unroll 8
    for (int c = 0; c < CC; c++)
        hb[(size_t)c * SS] = __float2bfloat16_rn(xb[(size_t)c * SS] * scale * gamma[c]);
}

// ---------------------------------------------------------------------------
// QKV projection: D[co][s] = W[co][:] . hn[:][s]   A = W (MK), B = hn (KM)
// ---------------------------------------------------------------------------
__global__ void __launch_bounds__(128) qkv_kernel(
    const float* __restrict__ bq, const float* __restrict__ bk,
    const float* __restrict__ bv) {

    int which = blockIdx.z % 3;
    int b     = blockIdx.z / 3;
    const __nv_bfloat16* W = g_w[which];
    const float* bias = which == 0 ? bq : (which == 1 ? bk : bv);
    __nv_bfloat16* Cout = (which == 0 ? g_q : (which == 1 ? g_k : g_v)) + (size_t)b * CC * SS;
    const __nv_bfloat16* HN = g_hn + (size_t)b * CC * SS;

    int m0 = blockIdx.y * 128, n0 = blockIdx.x * 128;
    GEMM_VARS
    uint32_t tbA = sbase, tbB = sbase + STAGES * SZ_MK;

    for (int s = 0; s < STAGES - 1; s++) {
        stageMK(tbA + s * SZ_MK, W, CC, m0, s * KSLAB, tid);
        stageKM(tbB + s * SZ_KM, HN, SS, s * KSLAB, n0, tid);
        cp_commit();
    }
    const int nIt = CC / KSLAB;   // 16
    for (int i = 0; i < nIt; i++) {
        cp_wait<STAGES - 2>();
        __syncthreads();
        int sl = i % STAGES;
        SLAB_COMPUTE(fragA_MK, fragB_KM, tbA + sl * SZ_MK, tbB + sl * SZ_KM);
        int pf = i + STAGES - 1;
        if (pf < nIt) {
            int ps = pf % STAGES;
            stageMK(tbA + ps * SZ_MK, W, CC, m0, pf * KSLAB, tid);
            stageKM(tbB + ps * SZ_KM, HN, SS, pf * KSLAB, n0, tid);
            cp_commit();
        }
    }

#pragma unroll
    for (int mt = 0; mt < 4; mt++) {
        int m = m0 + wm + mt * 16 + qr;
        float bi0 = bias[m], bi1 = bias[m + 8];
#pragma unroll
        for (int nt = 0; nt < 8; nt++) {
            int n = n0 + wn + nt * 8 + qc * 2;
            *(__nv_bfloat162*)&Cout[(size_t)m * SS + n] =
                __floats2bfloat162_rn(acc[mt][nt][0] + bi0, acc[mt][nt][1] + bi0);
            *(__nv_bfloat162*)&Cout[(size_t)(m + 8) * SS + n] =
                __floats2bfloat162_rn(acc[mt][nt][2] + bi1, acc[mt][nt][3] + bi1);
        }
    }
}

// ---------------------------------------------------------------------------
// QK^T (allowed tiles only): A = Q (KM), B = K (KM); write exp(scores) bf16
// ---------------------------------------------------------------------------
__global__ void __launch_bounds__(128) qk_kernel() {
    int b  = blockIdx.z;
    int m0 = blockIdx.y * 128;   // sq
    int n0 = blockIdx.x * 128;   // sk
    if (n0 / NHW > m0 / NHW) return;

    const __nv_bfloat16* Q = g_q + (size_t)b * CC * SS;
    const __nv_bfloat16* K = g_k + (size_t)b * CC * SS;
    GEMM_VARS
    uint32_t tbA = sbase, tbB = sbase + STAGES * SZ_KM;

    for (int s = 0; s < STAGES - 1; s++) {
        stageKM(tbA + s * SZ_KM, Q, SS, s * KSLAB, m0, tid);
        stageKM(tbB + s * SZ_KM, K, SS, s * KSLAB, n0, tid);
        cp_commit();
    }
    const int nIt = CC / KSLAB;
    for (int i = 0; i < nIt; i++) {
        cp_wait<STAGES - 2>();
        __syncthreads();
        int sl = i % STAGES;
        SLAB_COMPUTE(fragA_KM, fragB_KM, tbA + sl * SZ_KM, tbB + sl * SZ_KM);
        int pf = i + STAGES - 1;
        if (pf < nIt) {
            int ps = pf % STAGES;
            stageKM(tbA + ps * SZ_KM, Q, SS, pf * KSLAB, m0, tid);
            stageKM(tbB + ps * SZ_KM, K, SS, pf * KSLAB, n0, tid);
            cp_commit();
        }
    }

    __nv_bfloat16* P = g_p + (size_t)b * SS * SS;
#pragma unroll
    for (int mt = 0; mt < 4; mt++) {
        int m = m0 + wm + mt * 16 + qr;
#pragma unroll
        for (int nt = 0; nt < 8; nt++) {
            int n = n0 + wn + nt * 8 + qc * 2;
            *(__nv_bfloat162*)&P[(size_t)m * SS + n] =
                __floats2bfloat162_rn(__expf(acc[mt][nt][0] * INV_SQRT_C),
                                      __expf(acc[mt][nt][1] * INV_SQRT_C));
            *(__nv_bfloat162*)&P[(size_t)(m + 8) * SS + n] =
                __floats2bfloat162_rn(__expf(acc[mt][nt][2] * INV_SQRT_C),
                                      __expf(acc[mt][nt][3] * INV_SQRT_C));
        }
    }
}

// ---------------------------------------------------------------------------
// row sums of exp(scores): g_rsum[b][sq] = sum_k P[sq][k]
// ---------------------------------------------------------------------------
__global__ void __launch_bounds__(256) rsum_kernel() {
    int sq = blockIdx.x;
    int b  = blockIdx.y;
    const __nv_bfloat162* row2 = (const __nv_bfloat162*)(g_p + ((size_t)b * SS + sq) * SS);
    int L = (sq / NHW + 1) * NHW;
    int n2 = L >> 9;
    int tid = threadIdx.x, lane = tid & 31, wid = tid >> 5;

    __shared__ float red[8];
    float s = 0.f;
#pragma unroll
    for (int i = 0; i < 16; i++)
        if (i < n2) {
            float2 v = __bfloat1622float2(row2[i * 256 + tid]);
            s += v.x + v.y;
        }
#pragma unroll
    for (int o = 16; o > 0; o >>= 1) s += __shfl_xor_sync(0xffffffffu, s, o);
    if (lane == 0) red[wid] = s;
    __syncthreads();
    if (tid == 0) {
        float S = 0.f;
#pragma unroll
        for (int i = 0; i < 8; i++) S += red[i];
        g_rsum[b * SS + sq] = S;
    }
}

// ---------------------------------------------------------------------------
// PV: D[sq][c] = (P[sq][:L] . v[c][:L]) / rsum[sq]
// ---------------------------------------------------------------------------
__global__ void __launch_bounds__(128) pv_kernel() {
    int b  = blockIdx.z;
    int m0 = blockIdx.y * 128;   // sq
    int n0 = blockIdx.x * 128;   // c
    int L  = (m0 / NHW + 1) * NHW;
    const int nIt = L / KSLAB;

    const __nv_bfloat16* P = g_p + (size_t)b * SS * SS;
    const __nv_bfloat16* V = g_v + (size_t)b * CC * SS;
    GEMM_VARS
    uint32_t tbA = sbase, tbB = sbase + STAGES * SZ_MK;

    for (int s = 0; s < STAGES - 1; s++) {
        stageMK(tbA + s * SZ_MK, P, SS, m0, s * KSLAB, tid);
        stageMK(tbB + s * SZ_MK, V, SS, n0, s * KSLAB, tid);
        cp_commit();
    }
    for (int i = 0; i < nIt; i++) {
        cp_wait<STAGES - 2>();
        __syncthreads();
        int sl = i % STAGES;
        SLAB_COMPUTE(fragA_MK, fragB_MK, tbA + sl * SZ_MK, tbB + sl * SZ_MK);
        int pf = i + STAGES - 1;
        if (pf < nIt) {
            int ps = pf % STAGES;
            stageMK(tbA + ps * SZ_MK, P, SS, m0, pf * KSLAB, tid);
            stageMK(tbB + ps * SZ_MK, V, SS, n0, pf * KSLAB, tid);
            cp_commit();
        }
    }

    __nv_bfloat16* O = g_o + (size_t)b * SS * CC;
#pragma unroll
    for (int mt = 0; mt < 4; mt++) {
        int m = m0 + wm + mt * 16 + qr;
        float inv0 = 1.f / g_rsum[b * SS + m];
        float inv1 = 1.f / g_rsum[b * SS + m + 8];
#pragma unroll
        for (int nt = 0; nt < 8; nt++) {
            int n = n0 + wn + nt * 8 + qc * 2;
            *(__nv_bfloat162*)&O[(size_t)m * CC + n] =
                __floats2bfloat162_rn(acc[mt][nt][0] * inv0, acc[mt][nt][1] * inv0);
            *(__nv_bfloat162*)&O[(size_t)(m + 8) * CC + n] =
                __floats2bfloat162_rn(acc[mt][nt][2] * inv1, acc[mt][nt][3] * inv1);
        }
    }
}

// ---------------------------------------------------------------------------
// O-proj + residual (fp32 out): A = wo (MK), B = g_o (MK rows s)
// ---------------------------------------------------------------------------
__global__ void __launch_bounds__(128) oproj_kernel(
    const float* __restrict__ bo, const float* __restrict__ x,
    float* __restrict__ out) {

    int b  = blockIdx.z;
    int m0 = blockIdx.y * 128;   // c_out
    int n0 = blockIdx.x * 128;   // s

    const __nv_bfloat16* W = g_w[3];
    const __nv_bfloat16* O = g_o + (size_t)b * SS * CC;
    GEMM_VARS
    uint32_t tbA = sbase, tbB = sbase + STAGES * SZ_MK;

    for (int s = 0; s < STAGES - 1; s++) {
        stageMK(tbA + s * SZ_MK, W, CC, m0, s * KSLAB, tid);
        stageMK(tbB + s * SZ_MK, O, CC, n0, s * KSLAB, tid);
        cp_commit();
    }
    const int nIt = CC / KSLAB;
    for (int i = 0; i < nIt; i++) {
        cp_wait<STAGES - 2>();
        __syncthreads();
        int sl = i % STAGES;
        SLAB_COMPUTE(fragA_MK, fragB_MK, tbA + sl * SZ_MK, tbB + sl * SZ_MK);
        int pf = i + STAGES - 1;
        if (pf < nIt) {
            int ps = pf % STAGES;
            stageMK(tbA + ps * SZ_MK, W, CC, m0, pf * KSLAB, tid);
            stageMK(tbB + ps * SZ_MK, O, CC, n0, pf * KSLAB, tid);
            cp_commit();
        }
    }

#pragma unroll
    for (int mt = 0; mt < 4; mt++) {
        int m = m0 + wm + mt * 16 + qr;
        float bi0 = bo[m], bi1 = bo[m + 8];
#pragma unroll
        for (int nt = 0; nt < 8; nt++) {
            int n = n0 + wn + nt * 8 + qc * 2;
            const float2 x0 = *(const float2*)&x[((size_t)b * CC + m) * SS + n];
            const float2 x1 = *(const float2*)&x[((size_t)b * CC + m + 8) * SS + n];
            float2 v0 = make_float2(acc[mt][nt][0] + bi0 + x0.x, acc[mt][nt][1] + bi0 + x0.y);
            float2 v1 = make_float2(acc[mt][nt][2] + bi1 + x1.x, acc[mt][nt][3] + bi1 + x1.y);
            *(float2*)&out[((size_t)b * CC + m) * SS + n]     = v0;
            *(float2*)&out[((size_t)b * CC + m + 8) * SS + n] = v1;
        }
    }
}

// ---------------------------------------------------------------------------
extern "C" void kernel_launch(void* const* d_in, const int* in_sizes, int n_in,
                              void* d_out, int out_size) {
    const float* x     = (const float*)d_in[0];
    const float* gamma = (const float*)d_in[1];
    const float* wq    = (const float*)d_in[2];
    const float* bq    = (const float*)d_in[3];
    const float* wk    = (const float*)d_in[4];
    const float* bk    = (const float*)d_in[5];
    const float* wv    = (const float*)d_in[6];
    const float* bv    = (const float*)d_in[7];
    const float* wo    = (const float*)d_in[8];
    const float* bo    = (const float*)d_in[9];
    float* out = (float*)d_out;

    static int attr_done = 0;
    if (!attr_done) {
        cudaFuncSetAttribute(qkv_kernel,   cudaFuncAttributeMaxDynamicSharedMemorySize, DYN_SMEM);
        cudaFuncSetAttribute(qk_kernel,    cudaFuncAttributeMaxDynamicSharedMemorySize, DYN_SMEM);
        cudaFuncSetAttribute(pv_kernel,    cudaFuncAttributeMaxDynamicSharedMemorySize, DYN_SMEM);
        cudaFuncSetAttribute(oproj_kernel, cudaFuncAttributeMaxDynamicSharedMemorySize, DYN_SMEM);
        attr_done = 1;
    }

    prep_w_kernel<<<dim3(CC * CC / 256, 4), 256>>>(wq, wk, wv, wo);
    rms_kernel<<<dim3(SS / 256, BB), 256>>>(x, gamma);
    qkv_kernel<<<dim3(SS / 128, CC / 128, BB * 3), 128, DYN_SMEM>>>(bq, bk, bv);
    qk_kernel<<<dim3(SS / 128, SS / 128, BB), 128, DYN_SMEM>>>();
    rsum_kernel<<<dim3(SS, BB), 256>>>();
    pv_kernel<<<dim3(CC / 128, SS / 128, BB), 128, DYN_SMEM>>>();
    oproj_kernel<<<dim3(SS / 128, CC / 128, BB), 128, DYN_SMEM>>>(bo, x, out);
}

// round 8
// speedup vs baseline: 1.3422x; 1.0174x over previous
#include <cuda_runtime.h>
#include <cuda_bf16.h>
#include <math.h>
#include <stdint.h>

#define BB 2
#define CC 512
#define SS 8192
#define NHW 1024
#define SQRT_C     22.627416997969522f
#define INV_SQRT_C 0.04419417382415922f

#define KSLAB 64
#define KMP 136                  // KM row stride (bf16): rows are k, 128 cols (+8 pad)
#define MKP 72                   // MK row stride (bf16): 128 rows, 64 k (+8 pad)
#define SZ_KM (KSLAB * KMP * 2)      // 17408 B  (64 k-rows)
#define SZ_MK (128 * MKP * 2)        // 18432 B
#define HALF_KM (32 * KMP * 2)       // 8704 B  (32-k half)
#define HALF_MK 64                   // 32 bf16 cols

#define SMEM_QK  (3 * 2 * SZ_KM)             // 104448
#define SMEM_QKV (3 * (SZ_MK + SZ_KM))       // 107520
#define SMEM_PV  (3 * 2 * SZ_MK)             // 110592

// Scratch (bf16 intermediates)
__device__ __nv_bfloat16 g_hn[(size_t)BB * CC * SS];   // [b][c][s]
__device__ __nv_bfloat16 g_q [(size_t)BB * CC * SS];   // [b][c][s]
__device__ __nv_bfloat16 g_k [(size_t)BB * CC * SS];   // [b][c][s]
__device__ __nv_bfloat16 g_v [(size_t)BB * CC * SS];   // [b][c][s]
__device__ __nv_bfloat16 g_p [(size_t)BB * SS * SS];   // [b][sq][sk] (exp, unnormalized)
__device__ __nv_bfloat16 g_o [(size_t)BB * SS * CC];   // [b][s][c]
__device__ __nv_bfloat16 g_w [4][(size_t)CC * CC];     // bf16 weights [co][ci]
__device__ float g_rsum[(size_t)BB * SS];              // row sums of exp

// ---------------------------------------------------------------------------
// PTX helpers
// ---------------------------------------------------------------------------
__device__ __forceinline__ uint32_t smaddr(const void* p) {
    return (uint32_t)__cvta_generic_to_shared(p);
}
__device__ __forceinline__ void cp16(uint32_t d, const void* s) {
    asm volatile("cp.async.cg.shared.global [%0], [%1], 16;\n" :: "r"(d), "l"(s));
}
__device__ __forceinline__ void cp_commit() { asm volatile("cp.async.commit_group;\n"); }
template<int N> __device__ __forceinline__ void cp_wait() {
    asm volatile("cp.async.wait_group %0;\n" :: "n"(N));
}
__device__ __forceinline__ void ldsm4(uint32_t* r, uint32_t a) {
    asm volatile("ldmatrix.sync.aligned.m8n8.x4.shared.b16 {%0,%1,%2,%3}, [%4];"
                 : "=r"(r[0]), "=r"(r[1]), "=r"(r[2]), "=r"(r[3]) : "r"(a));
}
__device__ __forceinline__ void ldsm4t(uint32_t* r, uint32_t a) {
    asm volatile("ldmatrix.sync.aligned.m8n8.x4.trans.shared.b16 {%0,%1,%2,%3}, [%4];"
                 : "=r"(r[0]), "=r"(r[1]), "=r"(r[2]), "=r"(r[3]) : "r"(a));
}
__device__ __forceinline__ void mma16816(float* c, const uint32_t* a, const uint32_t* b) {
    asm volatile("mma.sync.aligned.m16n8k16.row.col.f32.bf16.bf16.f32 "
                 "{%0,%1,%2,%3},{%4,%5,%6,%7},{%8,%9},{%0,%1,%2,%3};"
                 : "+f"(c[0]), "+f"(c[1]), "+f"(c[2]), "+f"(c[3])
                 : "r"(a[0]), "r"(a[1]), "r"(a[2]), "r"(a[3]), "r"(b[0]), "r"(b[1]));
}

// ---------------------------------------------------------------------------
// stagers: 64-K slab, 128 threads, 8 x 16B chunks each (1024 chunks)
// ---------------------------------------------------------------------------
__device__ __forceinline__ void stageKM(uint32_t dst, const __nv_bfloat16* g,
                                        int ld, int k0, int n0, int tid) {
#pragma unroll
    for (int j = 0; j < 8; j++) {
        int c = j * 128 + tid;
        int kr = c >> 4, off = (c & 15) << 3;
        cp16(dst + (uint32_t)(kr * KMP + off) * 2, g + (size_t)(k0 + kr) * ld + n0 + off);
    }
}
__device__ __forceinline__ void stageMK(uint32_t dst, const __nv_bfloat16* g,
                                        int ld, int r0, int k0, int tid) {
#pragma unroll
    for (int j = 0; j < 8; j++) {
        int c = j * 128 + tid;
        int row = c >> 3, off = (c & 7) << 3;
        cp16(dst + (uint32_t)(row * MKP + off) * 2, g + (size_t)(r0 + row) * ld + k0 + off);
    }
}

// ---------------------------------------------------------------------------
// fragment loaders (warp tile 64x64, 32-K half-slab)
// ---------------------------------------------------------------------------
__device__ __forceinline__ void fragA_KM(uint32_t a[4][4], uint32_t base,
                                         int wm, int lane, int ks) {
    int g = lane >> 3;
#pragma unroll
    for (int mt = 0; mt < 4; mt++) {
        int row = ks * 16 + ((g >> 1) << 3) + (lane & 7);
        int col = wm + mt * 16 + ((g & 1) << 3);
        ldsm4t(a[mt], base + (uint32_t)(row * KMP + col) * 2);
    }
}
__device__ __forceinline__ void fragA_MK(uint32_t a[4][4], uint32_t base,
                                         int wm, int lane, int ks) {
    int g = lane >> 3;
#pragma unroll
    for (int mt = 0; mt < 4; mt++) {
        int row = wm + mt * 16 + ((g & 1) << 3) + (lane & 7);
        int col = ks * 16 + ((g >> 1) << 3);
        ldsm4(a[mt], base + (uint32_t)(row * MKP + col) * 2);
    }
}
__device__ __forceinline__ void fragB_KM(uint32_t b[8][4], uint32_t base, int wn, int lane) {
    int g = lane >> 3;
#pragma unroll
    for (int nt = 0; nt < 8; nt++) {
        int row = (g << 3) + (lane & 7);
        int col = wn + nt * 8;
        ldsm4t(b[nt], base + (uint32_t)(row * KMP + col) * 2);
    }
}
__device__ __forceinline__ void fragB_MK(uint32_t b[8][4], uint32_t base, int wn, int lane) {
    int g = lane >> 3;
#pragma unroll
    for (int nt = 0; nt < 8; nt++) {
        int row = wn + nt * 8 + (lane & 7);
        int col = g << 3;
        ldsm4(b[nt], base + (uint32_t)(row * MKP + col) * 2);
    }
}

#define GEMM_VARS                                                     \
    extern __shared__ __align__(16) char dynsm[];                     \
    uint32_t sbase = smaddr(dynsm);                                   \
    int tid = threadIdx.x, lane = tid & 31, wid = tid >> 5;           \
    int wm = (wid >> 1) * 64, wn = (wid & 1) * 64;                    \
    int qr = lane >> 2, qc = lane & 3;                                \
    float acc[4][8][4];                                               \
    _Pragma("unroll") for (int mt = 0; mt < 4; mt++)                  \
    _Pragma("unroll") for (int nt = 0; nt < 8; nt++)                  \
    _Pragma("unroll") for (int i = 0; i < 4; i++) acc[mt][nt][i] = 0.f;

// one 32-K half-slab
#define SLAB_COMPUTE(FA, FB, baseA, baseB)                            \
    {                                                                 \
        uint32_t bfr[8][4];                                           \
        FB(bfr, (baseB), wn, lane);                                   \
        _Pragma("unroll")                                             \
        for (int ks = 0; ks < 2; ks++) {                              \
            uint32_t afr[4][4];                                       \
            FA(afr, (baseA), wm, lane, ks);                           \
            _Pragma("unroll") for (int mt = 0; mt < 4; mt++)          \
            _Pragma("unroll") for (int nt = 0; nt < 8; nt++)          \
                mma16816(acc[mt][nt], afr[mt], &bfr[nt][ks * 2]);     \
        }                                                             \
    }

// full 64-K slab = two halves
#define SLAB64(FA, FB, baseA, baseB, HA, HB)                          \
    SLAB_COMPUTE(FA, FB, (baseA), (baseB));                           \
    SLAB_COMPUTE(FA, FB, (baseA) + (HA), (baseB) + (HB));

#define ROT3(s0, s1, s2) { uint32_t _t = s0; s0 = s1; s1 = s2; s2 = _t; }

// ---------------------------------------------------------------------------
// prep: fp32 weights -> bf16
// ---------------------------------------------------------------------------
__global__ void prep_w_kernel(const float* __restrict__ wq, const float* __restrict__ wk,
                              const float* __restrict__ wv, const float* __restrict__ wo) {
    int which = blockIdx.y;
    const float* w = which == 0 ? wq : which == 1 ? wk : which == 2 ? wv : wo;
    int i = blockIdx.x * 256 + threadIdx.x;
    g_w[which][i] = __float2bfloat16_rn(w[i]);
}

// ---------------------------------------------------------------------------
// RMS norm (bf16 out, [c][s])
// ---------------------------------------------------------------------------
__global__ void rms_kernel(const float* __restrict__ x,
                           const float* __restrict__ gamma) {
    int s = blockIdx.x * blockDim.x + threadIdx.x;
    int b = blockIdx.y;
    const float* xb = x + (size_t)b * CC * SS + s;
    float ss = 0.f;
#pragma unroll 8
    for (int c = 0; c < CC; c++) {
        float v = xb[(size_t)c * SS];
        ss += v * v;
    }
    float scale = SQRT_C / fmaxf(sqrtf(ss), 1e-12f);
    __nv_bfloat16* hb = g_hn + (size_t)b * CC * SS + s;
#pragma unroll 8
    for (int c = 0; c < CC; c++)
        hb[(size_t)c * SS] = __float2bfloat16_rn(xb[(size_t)c * SS] * scale * gamma[c]);
}

// ---------------------------------------------------------------------------
// QKV projection: D[co][s] = W[co][:] . hn[:][s]   A = W (MK), B = hn (KM)
// ---------------------------------------------------------------------------
__global__ void __launch_bounds__(128) qkv_kernel(
    const float* __restrict__ bq, const float* __restrict__ bk,
    const float* __restrict__ bv) {

    int which = blockIdx.z % 3;
    int b     = blockIdx.z / 3;
    const __nv_bfloat16* W = g_w[which];
    const float* bias = which == 0 ? bq : (which == 1 ? bk : bv);
    __nv_bfloat16* Cout = (which == 0 ? g_q : (which == 1 ? g_k : g_v)) + (size_t)b * CC * SS;
    const __nv_bfloat16* HN = g_hn + (size_t)b * CC * SS;

    int m0 = blockIdx.y * 128, n0 = blockIdx.x * 128;
    GEMM_VARS
    uint32_t a0 = sbase, a1 = a0 + SZ_MK, a2 = a1 + SZ_MK;
    uint32_t b0 = sbase + 3 * SZ_MK, b1 = b0 + SZ_KM, b2 = b1 + SZ_KM;

    stageMK(a0, W, CC, m0, 0, tid);     stageKM(b0, HN, SS, 0, n0, tid);     cp_commit();
    stageMK(a1, W, CC, m0, KSLAB, tid); stageKM(b1, HN, SS, KSLAB, n0, tid); cp_commit();

    const int nIt = CC / KSLAB;   // 8
#pragma unroll
    for (int i = 0; i < nIt; i++) {
        cp_wait<1>();
        __syncthreads();
        SLAB64(fragA_MK, fragB_KM, a0, b0, HALF_MK, HALF_KM);
        if (i + 2 < nIt) {
            stageMK(a2, W, CC, m0, (i + 2) * KSLAB, tid);
            stageKM(b2, HN, SS, (i + 2) * KSLAB, n0, tid);
            cp_commit();
        }
        ROT3(a0, a1, a2); ROT3(b0, b1, b2);
    }

#pragma unroll
    for (int mt = 0; mt < 4; mt++) {
        int m = m0 + wm + mt * 16 + qr;
        float bi0 = bias[m], bi1 = bias[m + 8];
#pragma unroll
        for (int nt = 0; nt < 8; nt++) {
            int n = n0 + wn + nt * 8 + qc * 2;
            *(__nv_bfloat162*)&Cout[(size_t)m * SS + n] =
                __floats2bfloat162_rn(acc[mt][nt][0] + bi0, acc[mt][nt][1] + bi0);
            *(__nv_bfloat162*)&Cout[(size_t)(m + 8) * SS + n] =
                __floats2bfloat162_rn(acc[mt][nt][2] + bi1, acc[mt][nt][3] + bi1);
        }
    }
}

// ---------------------------------------------------------------------------
// QK^T, compacted grid over allowed tiles; writes exp(scores) bf16
// ---------------------------------------------------------------------------
__global__ void __launch_bounds__(128) qk_kernel() {
    int b = blockIdx.z;
    int bi = blockIdx.x;
    int f = 0;
    while (bi >= 64 * (f + 1)) { bi -= 64 * (f + 1); f++; }
    int r  = bi / (8 * (f + 1));
    int nc = bi % (8 * (f + 1));
    int m0 = (f * 8 + r) * 128;   // sq
    int n0 = nc * 128;            // sk

    const __nv_bfloat16* Q = g_q + (size_t)b * CC * SS;
    const __nv_bfloat16* K = g_k + (size_t)b * CC * SS;
    GEMM_VARS
    uint32_t a0 = sbase, a1 = a0 + SZ_KM, a2 = a1 + SZ_KM;
    uint32_t b0 = sbase + 3 * SZ_KM, b1 = b0 + SZ_KM, b2 = b1 + SZ_KM;

    stageKM(a0, Q, SS, 0, m0, tid);     stageKM(b0, K, SS, 0, n0, tid);     cp_commit();
    stageKM(a1, Q, SS, KSLAB, m0, tid); stageKM(b1, K, SS, KSLAB, n0, tid); cp_commit();

    const int nIt = CC / KSLAB;   // 8
#pragma unroll
    for (int i = 0; i < nIt; i++) {
        cp_wait<1>();
        __syncthreads();
        SLAB64(fragA_KM, fragB_KM, a0, b0, HALF_KM, HALF_KM);
        if (i + 2 < nIt) {
            stageKM(a2, Q, SS, (i + 2) * KSLAB, m0, tid);
            stageKM(b2, K, SS, (i + 2) * KSLAB, n0, tid);
            cp_commit();
        }
        ROT3(a0, a1, a2); ROT3(b0, b1, b2);
    }

    __nv_bfloat16* P = g_p + (size_t)b * SS * SS;
#pragma unroll
    for (int mt = 0; mt < 4; mt++) {
        int m = m0 + wm + mt * 16 + qr;
#pragma unroll
        for (int nt = 0; nt < 8; nt++) {
            int n = n0 + wn + nt * 8 + qc * 2;
            *(__nv_bfloat162*)&P[(size_t)m * SS + n] =
                __floats2bfloat162_rn(__expf(acc[mt][nt][0] * INV_SQRT_C),
                                      __expf(acc[mt][nt][1] * INV_SQRT_C));
            *(__nv_bfloat162*)&P[(size_t)(m + 8) * SS + n] =
                __floats2bfloat162_rn(__expf(acc[mt][nt][2] * INV_SQRT_C),
                                      __expf(acc[mt][nt][3] * INV_SQRT_C));
        }
    }
}

// ---------------------------------------------------------------------------
// row sums of exp(scores)
// ---------------------------------------------------------------------------
__global__ void __launch_bounds__(256) rsum_kernel() {
    int sq = blockIdx.x;
    int b  = blockIdx.y;
    const __nv_bfloat162* row2 = (const __nv_bfloat162*)(g_p + ((size_t)b * SS + sq) * SS);
    int L = (sq / NHW + 1) * NHW;
    int n2 = L >> 9;
    int tid = threadIdx.x, lane = tid & 31, wid = tid >> 5;

    __shared__ float red[8];
    float s = 0.f;
#pragma unroll
    for (int i = 0; i < 16; i++)
        if (i < n2) {
            float2 v = __bfloat1622float2(row2[i * 256 + tid]);
            s += v.x + v.y;
        }
#pragma unroll
    for (int o = 16; o > 0; o >>= 1) s += __shfl_xor_sync(0xffffffffu, s, o);
    if (lane == 0) red[wid] = s;
    __syncthreads();
    if (tid == 0) {
        float S = 0.f;
#pragma unroll
        for (int i = 0; i < 8; i++) S += red[i];
        g_rsum[b * SS + sq] = S;
    }
}

// ---------------------------------------------------------------------------
// PV: D[sq][c] = (P[sq][:L] . v[c][:L]) / rsum[sq]
// ---------------------------------------------------------------------------
__global__ void __launch_bounds__(128) pv_kernel() {
    int b  = blockIdx.z;
    int m0 = blockIdx.y * 128;   // sq
    int n0 = blockIdx.x * 128;   // c
    int L  = (m0 / NHW + 1) * NHW;
    const int nIt = L / KSLAB;

    const __nv_bfloat16* P = g_p + (size_t)b * SS * SS;
    const __nv_bfloat16* V = g_v + (size_t)b * CC * SS;
    GEMM_VARS
    uint32_t a0 = sbase, a1 = a0 + SZ_MK, a2 = a1 + SZ_MK;
    uint32_t b0 = sbase + 3 * SZ_MK, b1 = b0 + SZ_MK, b2 = b1 + SZ_MK;

    stageMK(a0, P, SS, m0, 0, tid);     stageMK(b0, V, SS, n0, 0, tid);     cp_commit();
    stageMK(a1, P, SS, m0, KSLAB, tid); stageMK(b1, V, SS, n0, KSLAB, tid); cp_commit();

    for (int i = 0; i < nIt; i++) {
        cp_wait<1>();
        __syncthreads();
        SLAB64(fragA_MK, fragB_MK, a0, b0, HALF_MK, HALF_MK);
        if (i + 2 < nIt) {
            stageMK(a2, P, SS, m0, (i + 2) * KSLAB, tid);
            stageMK(b2, V, SS, n0, (i + 2) * KSLAB, tid);
            cp_commit();
        }
        ROT3(a0, a1, a2); ROT3(b0, b1, b2);
    }

    __nv_bfloat16* O = g_o + (size_t)b * SS * CC;
#pragma unroll
    for (int mt = 0; mt < 4; mt++) {
        int m = m0 + wm + mt * 16 + qr;
        float inv0 = 1.f / g_rsum[b * SS + m];
        float inv1 = 1.f / g_rsum[b * SS + m + 8];
#pragma unroll
        for (int nt = 0; nt < 8; nt++) {
            int n = n0 + wn + nt * 8 + qc * 2;
            *(__nv_bfloat162*)&O[(size_t)m * CC + n] =
                __floats2bfloat162_rn(acc[mt][nt][0] * inv0, acc[mt][nt][1] * inv0);
            *(__nv_bfloat162*)&O[(size_t)(m + 8) * CC + n] =
                __floats2bfloat162_rn(acc[mt][nt][2] * inv1, acc[mt][nt][3] * inv1);
        }
    }
}

// ---------------------------------------------------------------------------
// O-proj + residual (fp32 out): A = wo (MK), B = g_o (MK rows s)
// ---------------------------------------------------------------------------
__global__ void __launch_bounds__(128) oproj_kernel(
    const float* __restrict__ bo, const float* __restrict__ x,
    float* __restrict__ out) {

    int b  = blockIdx.z;
    int m0 = blockIdx.y * 128;   // c_out
    int n0 = blockIdx.x * 128;   // s

    const __nv_bfloat16* W = g_w[3];
    const __nv_bfloat16* O = g_o + (size_t)b * SS * CC;
    GEMM_VARS
    uint32_t a0 = sbase, a1 = a0 + SZ_MK, a2 = a1 + SZ_MK;
    uint32_t b0 = sbase + 3 * SZ_MK, b1 = b0 + SZ_MK, b2 = b1 + SZ_MK;

    stageMK(a0, W, CC, m0, 0, tid);     stageMK(b0, O, CC, n0, 0, tid);     cp_commit();
    stageMK(a1, W, CC, m0, KSLAB, tid); stageMK(b1, O, CC, n0, KSLAB, tid); cp_commit();

    const int nIt = CC / KSLAB;   // 8
#pragma unroll
    for (int i = 0; i < nIt; i++) {
        cp_wait<1>();
        __syncthreads();
        SLAB64(fragA_MK, fragB_MK, a0, b0, HALF_MK, HALF_MK);
        if (i + 2 < nIt) {
            stageMK(a2, W, CC, m0, (i + 2) * KSLAB, tid);
            stageMK(b2, O, CC, n0, (i + 2) * KSLAB, tid);
            cp_commit();
        }
        ROT3(a0, a1, a2); ROT3(b0, b1, b2);
    }

#pragma unroll
    for (int mt = 0; mt < 4; mt++) {
        int m = m0 + wm + mt * 16 + qr;
        float bi0 = bo[m], bi1 = bo[m + 8];
#pragma unroll
        for (int nt = 0; nt < 8; nt++) {
            int n = n0 + wn + nt * 8 + qc * 2;
            const float2 x0 = *(const float2*)&x[((size_t)b * CC + m) * SS + n];
            const float2 x1 = *(const float2*)&x[((size_t)b * CC + m + 8) * SS + n];
            float2 v0 = make_float2(acc[mt][nt][0] + bi0 + x0.x, acc[mt][nt][1] + bi0 + x0.y);
            float2 v1 = make_float2(acc[mt][nt][2] + bi1 + x1.x, acc[mt][nt][3] + bi1 + x1.y);
            *(float2*)&out[((size_t)b * CC + m) * SS + n]     = v0;
            *(float2*)&out[((size_t)b * CC + m + 8) * SS + n] = v1;
        }
    }
}

// ---------------------------------------------------------------------------
extern "C" void kernel_launch(void* const* d_in, const int* in_sizes, int n_in,
                              void* d_out, int out_size) {
    const float* x     = (const float*)d_in[0];
    const float* gamma = (const float*)d_in[1];
    const float* wq    = (const float*)d_in[2];
    const float* bq    = (const float*)d_in[3];
    const float* wk    = (const float*)d_in[4];
    const float* bk    = (const float*)d_in[5];
    const float* wv    = (const float*)d_in[6];
    const float* bv    = (const float*)d_in[7];
    const float* wo    = (const float*)d_in[8];
    const float* bo    = (const float*)d_in[9];
    float* out = (float*)d_out;

    static int attr_done = 0;
    if (!attr_done) {
        cudaFuncSetAttribute(qkv_kernel,   cudaFuncAttributeMaxDynamicSharedMemorySize, SMEM_QKV);
        cudaFuncSetAttribute(qk_kernel,    cudaFuncAttributeMaxDynamicSharedMemorySize, SMEM_QK);
        cudaFuncSetAttribute(pv_kernel,    cudaFuncAttributeMaxDynamicSharedMemorySize, SMEM_PV);
        cudaFuncSetAttribute(oproj_kernel, cudaFuncAttributeMaxDynamicSharedMemorySize, SMEM_PV);
        attr_done = 1;
    }

    prep_w_kernel<<<dim3(CC * CC / 256, 4), 256>>>(wq, wk, wv, wo);
    rms_kernel<<<dim3(SS / 256, BB), 256>>>(x, gamma);
    qkv_kernel<<<dim3(SS / 128, CC / 128, BB * 3), 128, SMEM_QKV>>>(bq, bk, bv);
    qk_kernel<<<dim3(2304, 1, BB), 128, SMEM_QK>>>();
    rsum_kernel<<<dim3(SS, BB), 256>>>();
    pv_kernel<<<dim3(CC / 128, SS / 128, BB), 128, SMEM_PV>>>();
    oproj_kernel<<<dim3(SS / 128, CC / 128, BB), 128, SMEM_PV>>>(bo, x, out);
}